// round 3
// baseline (speedup 1.0000x reference)
#include <cuda_runtime.h>
#include <cuda_bf16.h>
#include <cstdint>
#include <cstddef>
#include <math.h>

// ---------------- problem dims ----------------
#define BB 4096
#define HH 2048
#define K1 6144          // K for GEMM1: [x|h|c]
#define N1 8192          // N for GEMM1: 4 gates * 2048

// ---------------- GEMM tile config ----------------
#define BM 128
#define BN 128
#define BK 32            // bf16 elements per chunk
#define LDT 40           // smem row stride in bf16 (80 bytes: 64 data + 16 pad)
#define TILE_BYTES (BM * LDT * 2)            // 10240
#define ST_AH 0
#define ST_AL TILE_BYTES
#define ST_BH (2 * TILE_BYTES)
#define ST_BL (3 * TILE_BYTES)
#define STAGE_BYTES (4 * TILE_BYTES)         // 40960
#define NSTAGE 3
#define SMEM_DYN (NSTAGE * STAGE_BYTES + 128)

// ---------------- device scratch (static; alloc APIs are forbidden) ------
__device__ __nv_bfloat16 g_A1hi[(size_t)BB * K1];
__device__ __nv_bfloat16 g_A1lo[(size_t)BB * K1];
__device__ __nv_bfloat16 g_W1hi[(size_t)N1 * K1];
__device__ __nv_bfloat16 g_W1lo[(size_t)N1 * K1];
__device__ __nv_bfloat16 g_W2hi[(size_t)HH * HH];
__device__ __nv_bfloat16 g_W2lo[(size_t)HH * HH];
__device__ __nv_bfloat16 g_A2hi[(size_t)BB * HH];
__device__ __nv_bfloat16 g_A2lo[(size_t)BB * HH];
__device__ float         g_C[(size_t)BB * N1];

// ---------------- helpers ----------------
__device__ __forceinline__ uint32_t smem_u32(const void* p) {
    uint32_t a;
    asm("{ .reg .u64 t; cvta.to.shared.u64 t, %1; cvt.u32.u64 %0, t; }" : "=r"(a) : "l"(p));
    return a;
}

__device__ __forceinline__ void cp_async16(uint32_t dst, const void* src) {
    asm volatile("cp.async.cg.shared.global [%0], [%1], 16;" :: "r"(dst), "l"(src));
}

__device__ __forceinline__ void ldmatrix_x4(uint32_t* r, uint32_t addr) {
    asm volatile("ldmatrix.sync.aligned.m8n8.x4.shared.b16 {%0,%1,%2,%3}, [%4];"
        : "=r"(r[0]), "=r"(r[1]), "=r"(r[2]), "=r"(r[3]) : "r"(addr));
}

__device__ __forceinline__ uint32_t lds32(uint32_t addr) {
    uint32_t v;
    asm volatile("ld.shared.b32 %0, [%1];" : "=r"(v) : "r"(addr));
    return v;
}

__device__ __forceinline__ void mma_16816(float* c, const uint32_t* a, const uint32_t* b) {
    asm volatile(
        "mma.sync.aligned.m16n8k16.row.col.f32.bf16.bf16.f32 "
        "{%0,%1,%2,%3}, {%4,%5,%6,%7}, {%8,%9}, {%0,%1,%2,%3};"
        : "+f"(c[0]), "+f"(c[1]), "+f"(c[2]), "+f"(c[3])
        : "r"(a[0]), "r"(a[1]), "r"(a[2]), "r"(a[3]), "r"(b[0]), "r"(b[1]));
}

__device__ __forceinline__ void split_store(__nv_bfloat16* hi, __nv_bfloat16* lo,
                                            size_t i, float v) {
    __nv_bfloat16 h = __float2bfloat16(v);
    hi[i] = h;
    lo[i] = __float2bfloat16(v - __bfloat162float(h));
}

// ---------------- packing kernels ----------------
__global__ void pack_A1(const float* __restrict__ x, const float* __restrict__ h,
                        const float* __restrict__ c) {
    size_t n = (size_t)BB * K1;
    for (size_t i = blockIdx.x * (size_t)blockDim.x + threadIdx.x; i < n;
         i += (size_t)gridDim.x * blockDim.x) {
        size_t m = i / K1;
        int k = (int)(i - m * K1);
        float v;
        if (k < HH)          v = x[m * HH + k];
        else if (k < 2 * HH) v = h[m * HH + (k - HH)];
        else                 v = c[m * HH + (k - 2 * HH)];
        split_store(g_A1hi, g_A1lo, i, v);
    }
}

__global__ void pack_W1(const float* __restrict__ Wix, const float* __restrict__ Wfx,
                        const float* __restrict__ Wcx, const float* __restrict__ Wox,
                        const float* __restrict__ Wih, const float* __restrict__ Wic,
                        const float* __restrict__ Wfh, const float* __restrict__ Wfc,
                        const float* __restrict__ Wch, const float* __restrict__ Woh) {
    size_t n = (size_t)N1 * K1;
    for (size_t i = blockIdx.x * (size_t)blockDim.x + threadIdx.x; i < n;
         i += (size_t)gridDim.x * blockDim.x) {
        size_t row = i / K1;
        int k = (int)(i - row * K1);
        int gate = (int)(row >> 11);
        int j = (int)(row & 2047);
        int seg = k >> 11;
        int kk = k & 2047;
        const float* W = nullptr;
        switch (gate * 3 + seg) {
            case 0:  W = Wix; break;
            case 1:  W = Wih; break;
            case 2:  W = Wic; break;
            case 3:  W = Wfx; break;
            case 4:  W = Wfh; break;
            case 5:  W = Wfc; break;
            case 6:  W = Wcx; break;
            case 7:  W = Wch; break;
            case 9:  W = Wox; break;
            case 10: W = Woh; break;
            default: break;   // gate g/o c-slot: zero
        }
        float v = W ? W[(size_t)j * HH + kk] : 0.0f;
        split_store(g_W1hi, g_W1lo, i, v);
    }
}

__global__ void pack_W2(const float* __restrict__ Woc) {
    size_t n = (size_t)HH * HH;
    for (size_t i = blockIdx.x * (size_t)blockDim.x + threadIdx.x; i < n;
         i += (size_t)gridDim.x * blockDim.x) {
        split_store(g_W2hi, g_W2lo, i, Woc[i]);
    }
}

// ---------------- GEMM: C = Ahi*Bhi^T + Ahi*Blo^T + Alo*Bhi^T ---------------
// sm80-style: cp.async 3-stage pipeline + mma.sync m16n8k16 bf16.
__global__ void __launch_bounds__(256, 1)
gemm_kernel(int which) {
    const __nv_bfloat16 *Ahi, *Alo, *Bhi, *Blo;
    float* C;
    int K;
    if (which == 0) {
        Ahi = g_A1hi; Alo = g_A1lo; Bhi = g_W1hi; Blo = g_W1lo;
        C = g_C; K = K1;
    } else {
        Ahi = g_A2hi; Alo = g_A2lo; Bhi = g_W2hi; Blo = g_W2lo;
        C = g_C + 2 * HH;   // gate-g column region (already consumed by ew1)
        K = HH;
    }
    const int ldc = N1;
    const size_t arow0 = (size_t)blockIdx.x * BM;
    const size_t brow0 = (size_t)blockIdx.y * BN;
    const int nchunk = K / BK;
    const int tid = threadIdx.x;
    const int lane = tid & 31;
    const int wid = tid >> 5;
    const int warpM = wid & 3;   // 4 warps over M: 32 rows each
    const int warpN = wid >> 2;  // 2 warps over N: 64 cols each

    extern __shared__ char dsmem[];
    const uint32_t sb = (smem_u32(dsmem) + 127u) & ~127u;

    // loader for chunk j into stage s (always commits, possibly empty group)
    auto load_chunk = [&](int j, int s) {
        if (j < nchunk) {
            const uint32_t stage = sb + s * STAGE_BYTES;
            const size_t kof = (size_t)j * BK;
            #pragma unroll
            for (int it = 0; it < 8; ++it) {
                int idx = tid + it * 256;        // 0..2047
                int g = idx & 3;                 // 16B segment within row (4 x 16B = 64B)
                int rs = idx >> 2;               // 0..511: tile-row id
                const __nv_bfloat16* src;
                uint32_t dstbase;
                int r;
                if (rs < 128)      { r = rs;       src = Ahi + (arow0 + r) * K + kof; dstbase = stage + ST_AH; }
                else if (rs < 256) { r = rs - 128; src = Alo + (arow0 + r) * K + kof; dstbase = stage + ST_AL; }
                else if (rs < 384) { r = rs - 256; src = Bhi + (brow0 + r) * K + kof; dstbase = stage + ST_BH; }
                else               { r = rs - 384; src = Blo + (brow0 + r) * K + kof; dstbase = stage + ST_BL; }
                uint32_t dst = dstbase + (uint32_t)r * (LDT * 2) + (uint32_t)g * 16u;
                cp_async16(dst, (const void*)(src + g * 8));
            }
        }
        asm volatile("cp.async.commit_group;" ::: "memory");
    };

    float acc[2][8][4];
    #pragma unroll
    for (int mi = 0; mi < 2; ++mi)
        #pragma unroll
        for (int ni = 0; ni < 8; ++ni)
            #pragma unroll
            for (int q = 0; q < 4; ++q) acc[mi][ni][q] = 0.0f;

    load_chunk(0, 0);
    load_chunk(1, 1);

    for (int j = 0; j < nchunk; ++j) {
        const int s = j % NSTAGE;
        asm volatile("cp.async.wait_group 1;" ::: "memory");
        __syncthreads();
        load_chunk(j + 2, (j + 2) % NSTAGE);

        const uint32_t stage = sb + s * STAGE_BYTES;
        const uint32_t a_hi = stage + ST_AH + (warpM * 32 + (lane & 15)) * (LDT * 2) + (lane >> 4) * 16;
        const uint32_t a_lo = stage + ST_AL + (warpM * 32 + (lane & 15)) * (LDT * 2) + (lane >> 4) * 16;
        const uint32_t b_hi0 = stage + ST_BH + (warpN * 64 + (lane >> 2)) * (LDT * 2) + (lane & 3) * 4;
        const uint32_t b_lo0 = stage + ST_BL + (warpN * 64 + (lane >> 2)) * (LDT * 2) + (lane & 3) * 4;

        #pragma unroll
        for (int ks = 0; ks < 2; ++ks) {     // two k16 steps per BK=32 chunk
            const uint32_t koff = ks * 32;   // 16 bf16 = 32 bytes
            uint32_t ah[2][4], al[2][4];
            #pragma unroll
            for (int mi = 0; mi < 2; ++mi) {
                ldmatrix_x4(ah[mi], a_hi + mi * 16 * (LDT * 2) + koff);
                ldmatrix_x4(al[mi], a_lo + mi * 16 * (LDT * 2) + koff);
            }
            #pragma unroll
            for (int ni = 0; ni < 8; ++ni) {
                uint32_t bh[2], bl[2];
                const uint32_t bro = ni * 8 * (LDT * 2) + koff;
                bh[0] = lds32(b_hi0 + bro);
                bh[1] = lds32(b_hi0 + bro + 16);
                bl[0] = lds32(b_lo0 + bro);
                bl[1] = lds32(b_lo0 + bro + 16);
                #pragma unroll
                for (int mi = 0; mi < 2; ++mi) {
                    mma_16816(acc[mi][ni], ah[mi], bh);
                    mma_16816(acc[mi][ni], ah[mi], bl);
                    mma_16816(acc[mi][ni], al[mi], bh);
                }
            }
        }
        __syncthreads();
    }

    // epilogue: fp32 store
    #pragma unroll
    for (int mi = 0; mi < 2; ++mi) {
        const size_t m0 = arow0 + warpM * 32 + mi * 16 + (lane >> 2);
        #pragma unroll
        for (int ni = 0; ni < 8; ++ni) {
            const size_t n0 = brow0 + warpN * 64 + ni * 8 + (lane & 3) * 2;
            float2 v0 = make_float2(acc[mi][ni][0], acc[mi][ni][1]);
            float2 v1 = make_float2(acc[mi][ni][2], acc[mi][ni][3]);
            *reinterpret_cast<float2*>(C + m0 * ldc + n0)       = v0;
            *reinterpret_cast<float2*>(C + (m0 + 8) * ldc + n0) = v1;
        }
    }
}

// ---------------- elementwise 1: gates i,f,g -> c_next; pack A2 -------------
__global__ void ew1(const float* __restrict__ c,
                    const float* __restrict__ b_ix, const float* __restrict__ b_ih,
                    const float* __restrict__ b_ic,
                    const float* __restrict__ b_fx, const float* __restrict__ b_fh,
                    const float* __restrict__ b_fc,
                    const float* __restrict__ b_cx, const float* __restrict__ b_ch,
                    float* __restrict__ out) {
    const size_t n = (size_t)BB * HH;
    for (size_t i = blockIdx.x * (size_t)blockDim.x + threadIdx.x; i < n;
         i += (size_t)gridDim.x * blockDim.x) {
        size_t m = i / HH;
        int j = (int)(i - m * HH);
        const float* crow = g_C + m * (size_t)N1;
        float ip = crow[j]        + b_ix[j] + b_ih[j] + b_ic[j];
        float fp = crow[2048 + j] + b_fx[j] + b_fh[j] + b_fc[j];
        float gp = crow[4096 + j] + b_cx[j] + b_ch[j];
        float ii = 1.0f / (1.0f + expf(-ip));
        float ff = 1.0f / (1.0f + expf(-fp));
        float gg = tanhf(gp);
        float cn = ff * c[i] + ii * gg;
        out[2 * n + i] = cn;                       // c_next
        split_store(g_A2hi, g_A2lo, i, cn);        // A2 for GEMM2
    }
}

// ---------------- elementwise 2: o gate, h_next ----------------
__global__ void ew2(const float* __restrict__ b_ox, const float* __restrict__ b_oh,
                    const float* __restrict__ b_oc,
                    float* __restrict__ out) {
    const size_t n = (size_t)BB * HH;
    for (size_t i = blockIdx.x * (size_t)blockDim.x + threadIdx.x; i < n;
         i += (size_t)gridDim.x * blockDim.x) {
        size_t m = i / HH;
        int j = (int)(i - m * HH);
        const float* crow = g_C + m * (size_t)N1;
        float op = crow[6144 + j] + crow[4096 + j] + b_ox[j] + b_oh[j] + b_oc[j];
        float cn = out[2 * n + i];
        float t = tanhf(cn);
        float o = (1.0f / (1.0f + expf(-op))) * t;
        out[i] = o;           // o
        out[n + i] = o * t;   // h_next
    }
}

// ---------------- launch ----------------
extern "C" void kernel_launch(void* const* d_in, const int* in_sizes, int n_in,
                              void* d_out, int out_size) {
    const float* x    = (const float*)d_in[0];
    const float* h    = (const float*)d_in[1];
    const float* c    = (const float*)d_in[2];
    const float* W_ix = (const float*)d_in[3];
    const float* b_ix = (const float*)d_in[4];
    const float* W_fx = (const float*)d_in[5];
    const float* b_fx = (const float*)d_in[6];
    const float* W_cx = (const float*)d_in[7];
    const float* b_cx = (const float*)d_in[8];
    const float* W_ox = (const float*)d_in[9];
    const float* b_ox = (const float*)d_in[10];
    const float* W_ih = (const float*)d_in[11];
    const float* b_ih = (const float*)d_in[12];
    const float* W_ic = (const float*)d_in[13];
    const float* b_ic = (const float*)d_in[14];
    const float* W_fh = (const float*)d_in[15];
    const float* b_fh = (const float*)d_in[16];
    const float* W_fc = (const float*)d_in[17];
    const float* b_fc = (const float*)d_in[18];
    const float* W_ch = (const float*)d_in[19];
    const float* b_ch = (const float*)d_in[20];
    const float* W_oh = (const float*)d_in[21];
    const float* b_oh = (const float*)d_in[22];
    const float* W_oc = (const float*)d_in[23];
    const float* b_oc = (const float*)d_in[24];
    float* out = (float*)d_out;

    static int attr_done = 0;
    if (!attr_done) {
        cudaFuncSetAttribute(gemm_kernel, cudaFuncAttributeMaxDynamicSharedMemorySize, SMEM_DYN);
        attr_done = 1;
    }

    pack_A1<<<2048, 256>>>(x, h, c);
    pack_W1<<<8192, 256>>>(W_ix, W_fx, W_cx, W_ox, W_ih, W_ic, W_fh, W_fc, W_ch, W_oh);
    pack_W2<<<1024, 256>>>(W_oc);

    dim3 g1(BB / BM, N1 / BN);   // 32 x 64
    gemm_kernel<<<g1, 256, SMEM_DYN>>>(0);

    ew1<<<4096, 256>>>(c, b_ix, b_ih, b_ic, b_fx, b_fh, b_fc, b_cx, b_ch, out);

    dim3 g2(BB / BM, HH / BN);   // 32 x 16
    gemm_kernel<<<g2, 256, SMEM_DYN>>>(1);

    ew2<<<4096, 256>>>(b_ox, b_oh, b_oc, out);
}

// round 6
// speedup vs baseline: 1.2822x; 1.2822x over previous
#include <cuda_runtime.h>
#include <cuda_bf16.h>
#include <cstdint>
#include <cstddef>
#include <math.h>

// ---------------- problem dims ----------------
#define BB 4096
#define HH 2048
#define K1 6144          // K for GEMM1: [x|h|c]
#define N1 8192          // N for GEMM1: 4 gates * 2048

// ---------------- GEMM tile config ----------------
#define BM 128
#define BN 256
#define BK 32            // bf16 elements per chunk
#define LDT 40           // smem row stride in bf16 (80 bytes: 64 data + 16 pad)
#define A_TILE_BYTES (BM * LDT * 2)          // 10240
#define B_TILE_BYTES (BN * LDT * 2)          // 20480
#define ST_AH 0
#define ST_AL A_TILE_BYTES
#define ST_BH (2 * A_TILE_BYTES)
#define ST_BL (2 * A_TILE_BYTES + B_TILE_BYTES)
#define STAGE_BYTES (2 * A_TILE_BYTES + 2 * B_TILE_BYTES)   // 61440
#define NSTAGE 3
#define SMEM_DYN (NSTAGE * STAGE_BYTES + 128)

// ---------------- device scratch (static; alloc APIs are forbidden) ------
__device__ __nv_bfloat16 g_A1hi[(size_t)BB * K1];
__device__ __nv_bfloat16 g_A1lo[(size_t)BB * K1];
__device__ __nv_bfloat16 g_W1hi[(size_t)N1 * K1];
__device__ __nv_bfloat16 g_W1lo[(size_t)N1 * K1];
__device__ __nv_bfloat16 g_W2hi[(size_t)HH * HH];
__device__ __nv_bfloat16 g_W2lo[(size_t)HH * HH];
__device__ __nv_bfloat16 g_A2hi[(size_t)BB * HH];
__device__ __nv_bfloat16 g_A2lo[(size_t)BB * HH];
__device__ float         g_C[(size_t)BB * N1];

// ---------------- helpers ----------------
__device__ __forceinline__ uint32_t smem_u32(const void* p) {
    uint32_t a;
    asm("{ .reg .u64 t; cvta.to.shared.u64 t, %1; cvt.u32.u64 %0, t; }" : "=r"(a) : "l"(p));
    return a;
}

__device__ __forceinline__ void cp_async16(uint32_t dst, const void* src) {
    asm volatile("cp.async.cg.shared.global [%0], [%1], 16;" :: "r"(dst), "l"(src));
}

__device__ __forceinline__ void ldmatrix_x4(uint32_t* r, uint32_t addr) {
    asm volatile("ldmatrix.sync.aligned.m8n8.x4.shared.b16 {%0,%1,%2,%3}, [%4];"
        : "=r"(r[0]), "=r"(r[1]), "=r"(r[2]), "=r"(r[3]) : "r"(addr));
}

__device__ __forceinline__ uint32_t lds32(uint32_t addr) {
    uint32_t v;
    asm volatile("ld.shared.b32 %0, [%1];" : "=r"(v) : "r"(addr));
    return v;
}

__device__ __forceinline__ void mma_16816(float* c, const uint32_t* a, const uint32_t* b) {
    asm volatile(
        "mma.sync.aligned.m16n8k16.row.col.f32.bf16.bf16.f32 "
        "{%0,%1,%2,%3}, {%4,%5,%6,%7}, {%8,%9}, {%0,%1,%2,%3};"
        : "+f"(c[0]), "+f"(c[1]), "+f"(c[2]), "+f"(c[3])
        : "r"(a[0]), "r"(a[1]), "r"(a[2]), "r"(a[3]), "r"(b[0]), "r"(b[1]));
}

__device__ __forceinline__ void split_store(__nv_bfloat16* hi, __nv_bfloat16* lo,
                                            size_t i, float v) {
    __nv_bfloat16 h = __float2bfloat16(v);
    hi[i] = h;
    lo[i] = __float2bfloat16(v - __bfloat162float(h));
}

// ---------------- packing kernels ----------------
__global__ void pack_A1(const float* __restrict__ x, const float* __restrict__ h,
                        const float* __restrict__ c) {
    size_t n = (size_t)BB * K1;
    for (size_t i = blockIdx.x * (size_t)blockDim.x + threadIdx.x; i < n;
         i += (size_t)gridDim.x * blockDim.x) {
        size_t m = i / K1;
        int k = (int)(i - m * K1);
        float v;
        if (k < HH)          v = x[m * HH + k];
        else if (k < 2 * HH) v = h[m * HH + (k - HH)];
        else                 v = c[m * HH + (k - 2 * HH)];
        split_store(g_A1hi, g_A1lo, i, v);
    }
}

__global__ void pack_W1(const float* __restrict__ Wix, const float* __restrict__ Wfx,
                        const float* __restrict__ Wcx, const float* __restrict__ Wox,
                        const float* __restrict__ Wih, const float* __restrict__ Wic,
                        const float* __restrict__ Wfh, const float* __restrict__ Wfc,
                        const float* __restrict__ Wch, const float* __restrict__ Woh) {
    size_t n = (size_t)N1 * K1;
    for (size_t i = blockIdx.x * (size_t)blockDim.x + threadIdx.x; i < n;
         i += (size_t)gridDim.x * blockDim.x) {
        size_t row = i / K1;
        int k = (int)(i - row * K1);
        int gate = (int)(row >> 11);
        int j = (int)(row & 2047);
        int seg = k >> 11;
        int kk = k & 2047;
        const float* W = nullptr;
        switch (gate * 3 + seg) {
            case 0:  W = Wix; break;
            case 1:  W = Wih; break;
            case 2:  W = Wic; break;
            case 3:  W = Wfx; break;
            case 4:  W = Wfh; break;
            case 5:  W = Wfc; break;
            case 6:  W = Wcx; break;
            case 7:  W = Wch; break;
            case 9:  W = Wox; break;
            case 10: W = Woh; break;
            default: break;   // gate g/o c-slot: zero (never read: variable-K skips it)
        }
        float v = W ? W[(size_t)j * HH + kk] : 0.0f;
        split_store(g_W1hi, g_W1lo, i, v);
    }
}

__global__ void pack_W2(const float* __restrict__ Woc) {
    size_t n = (size_t)HH * HH;
    for (size_t i = blockIdx.x * (size_t)blockDim.x + threadIdx.x; i < n;
         i += (size_t)gridDim.x * blockDim.x) {
        split_store(g_W2hi, g_W2lo, i, Woc[i]);
    }
}

// ---------------- GEMM: C = Ahi*Bhi^T + Ahi*Blo^T + Alo*Bhi^T ---------------
// sm80-style: cp.async 3-stage pipeline + mma.sync m16n8k16 bf16.
// CTA tile 128x256, 8 warps as 2(M) x 4(N), warp tile 64x64.
__global__ void __launch_bounds__(256, 1)
gemm_kernel(int which) {
    const __nv_bfloat16 *Ahi, *Alo, *Bhi, *Blo;
    float* C;
    int K, Keff;
    const size_t brow0 = (size_t)blockIdx.y * BN;
    if (which == 0) {
        Ahi = g_A1hi; Alo = g_A1lo; Bhi = g_W1hi; Blo = g_W1lo;
        C = g_C; K = K1;
        Keff = (brow0 >= 4096) ? 4096 : 6144;   // gates g,o have zero c-slot
    } else {
        Ahi = g_A2hi; Alo = g_A2lo; Bhi = g_W2hi; Blo = g_W2lo;
        C = g_C + 2 * HH;   // gate-g column region (already consumed by ew1)
        K = HH; Keff = HH;
    }
    const int ldc = N1;
    const size_t arow0 = (size_t)blockIdx.x * BM;
    const int nchunk = Keff / BK;
    const int tid = threadIdx.x;
    const int lane = tid & 31;
    const int wid = tid >> 5;
    const int warpM = wid & 1;   // 2 warps over M: 64 rows each
    const int warpN = wid >> 1;  // 4 warps over N: 64 cols each

    extern __shared__ char dsmem[];
    const uint32_t sb = (smem_u32(dsmem) + 127u) & ~127u;

    // loader for chunk j into stage s (always commits, possibly empty group)
    auto load_chunk = [&](int j, int s) {
        if (j < nchunk) {
            const uint32_t stage = sb + s * STAGE_BYTES;
            const size_t kof = (size_t)j * BK;
            #pragma unroll
            for (int it = 0; it < 12; ++it) {
                int idx = tid + it * 256;        // 0..3071
                int g = idx & 3;                 // 16B segment within 64B row
                int rs = idx >> 2;               // 0..767: tile-row id
                const __nv_bfloat16* src;
                uint32_t dstbase;
                int r;
                if (rs < 128)      { r = rs;       src = Ahi + (arow0 + r) * K + kof; dstbase = stage + ST_AH; }
                else if (rs < 256) { r = rs - 128; src = Alo + (arow0 + r) * K + kof; dstbase = stage + ST_AL; }
                else if (rs < 512) { r = rs - 256; src = Bhi + (brow0 + r) * K + kof; dstbase = stage + ST_BH; }
                else               { r = rs - 512; src = Blo + (brow0 + r) * K + kof; dstbase = stage + ST_BL; }
                uint32_t dst = dstbase + (uint32_t)r * (LDT * 2) + (uint32_t)g * 16u;
                cp_async16(dst, (const void*)(src + g * 8));
            }
        }
        asm volatile("cp.async.commit_group;" ::: "memory");
    };

    float acc[4][8][4];
    #pragma unroll
    for (int mi = 0; mi < 4; ++mi)
        #pragma unroll
        for (int ni = 0; ni < 8; ++ni)
            #pragma unroll
            for (int q = 0; q < 4; ++q) acc[mi][ni][q] = 0.0f;

    load_chunk(0, 0);
    load_chunk(1, 1);

    for (int j = 0; j < nchunk; ++j) {
        const int s = j % NSTAGE;
        asm volatile("cp.async.wait_group 1;" ::: "memory");
        __syncthreads();
        load_chunk(j + 2, (j + 2) % NSTAGE);

        const uint32_t stage = sb + s * STAGE_BYTES;
        const uint32_t a_hi = stage + ST_AH + (warpM * 64 + (lane & 15)) * (LDT * 2) + (lane >> 4) * 16;
        const uint32_t a_lo = stage + ST_AL + (warpM * 64 + (lane & 15)) * (LDT * 2) + (lane >> 4) * 16;
        const uint32_t b_hi0 = stage + ST_BH + (warpN * 64 + (lane >> 2)) * (LDT * 2) + (lane & 3) * 4;
        const uint32_t b_lo0 = stage + ST_BL + (warpN * 64 + (lane >> 2)) * (LDT * 2) + (lane & 3) * 4;

        #pragma unroll
        for (int ks = 0; ks < 2; ++ks) {     // two k16 steps per BK=32 chunk
            const uint32_t koff = ks * 32;   // 16 bf16 = 32 bytes
            uint32_t ah[4][4], al[4][4];
            #pragma unroll
            for (int mi = 0; mi < 4; ++mi) {
                ldmatrix_x4(ah[mi], a_hi + mi * 16 * (LDT * 2) + koff);
                ldmatrix_x4(al[mi], a_lo + mi * 16 * (LDT * 2) + koff);
            }
            #pragma unroll
            for (int ni = 0; ni < 8; ++ni) {
                uint32_t bh[2], bl[2];
                const uint32_t bro = ni * 8 * (LDT * 2) + koff;
                bh[0] = lds32(b_hi0 + bro);
                bh[1] = lds32(b_hi0 + bro + 16);
                bl[0] = lds32(b_lo0 + bro);
                bl[1] = lds32(b_lo0 + bro + 16);
                #pragma unroll
                for (int mi = 0; mi < 4; ++mi) {
                    mma_16816(acc[mi][ni], ah[mi], bh);
                    mma_16816(acc[mi][ni], ah[mi], bl);
                    mma_16816(acc[mi][ni], al[mi], bh);
                }
            }
        }
        __syncthreads();
    }

    // epilogue: fp32 store
    #pragma unroll
    for (int mi = 0; mi < 4; ++mi) {
        const size_t m0 = arow0 + warpM * 64 + mi * 16 + (lane >> 2);
        #pragma unroll
        for (int ni = 0; ni < 8; ++ni) {
            const size_t n0 = brow0 + warpN * 64 + ni * 8 + (lane & 3) * 2;
            float2 v0 = make_float2(acc[mi][ni][0], acc[mi][ni][1]);
            float2 v1 = make_float2(acc[mi][ni][2], acc[mi][ni][3]);
            *reinterpret_cast<float2*>(C + m0 * ldc + n0)       = v0;
            *reinterpret_cast<float2*>(C + (m0 + 8) * ldc + n0) = v1;
        }
    }
}

// ---------------- elementwise 1: gates i,f,g -> c_next; pack A2 -------------
__global__ void ew1(const float* __restrict__ c,
                    const float* __restrict__ b_ix, const float* __restrict__ b_ih,
                    const float* __restrict__ b_ic,
                    const float* __restrict__ b_fx, const float* __restrict__ b_fh,
                    const float* __restrict__ b_fc,
                    const float* __restrict__ b_cx, const float* __restrict__ b_ch,
                    float* __restrict__ out) {
    const size_t n = (size_t)BB * HH;
    for (size_t i = blockIdx.x * (size_t)blockDim.x + threadIdx.x; i < n;
         i += (size_t)gridDim.x * blockDim.x) {
        size_t m = i / HH;
        int j = (int)(i - m * HH);
        const float* crow = g_C + m * (size_t)N1;
        float ip = crow[j]        + b_ix[j] + b_ih[j] + b_ic[j];
        float fp = crow[2048 + j] + b_fx[j] + b_fh[j] + b_fc[j];
        float gp = crow[4096 + j] + b_cx[j] + b_ch[j];
        float ii = 1.0f / (1.0f + expf(-ip));
        float ff = 1.0f / (1.0f + expf(-fp));
        float gg = tanhf(gp);
        float cn = ff * c[i] + ii * gg;
        out[2 * n + i] = cn;                       // c_next
        split_store(g_A2hi, g_A2lo, i, cn);        // A2 for GEMM2
    }
}

// ---------------- elementwise 2: o gate, h_next ----------------
__global__ void ew2(const float* __restrict__ b_ox, const float* __restrict__ b_oh,
                    const float* __restrict__ b_oc,
                    float* __restrict__ out) {
    const size_t n = (size_t)BB * HH;
    for (size_t i = blockIdx.x * (size_t)blockDim.x + threadIdx.x; i < n;
         i += (size_t)gridDim.x * blockDim.x) {
        size_t m = i / HH;
        int j = (int)(i - m * HH);
        const float* crow = g_C + m * (size_t)N1;
        float op = crow[6144 + j] + crow[4096 + j] + b_ox[j] + b_oh[j] + b_oc[j];
        float cn = out[2 * n + i];
        float t = tanhf(cn);
        float o = (1.0f / (1.0f + expf(-op))) * t;
        out[i] = o;           // o
        out[n + i] = o * t;   // h_next
    }
}

// ---------------- launch ----------------
extern "C" void kernel_launch(void* const* d_in, const int* in_sizes, int n_in,
                              void* d_out, int out_size) {
    const float* x    = (const float*)d_in[0];
    const float* h    = (const float*)d_in[1];
    const float* c    = (const float*)d_in[2];
    const float* W_ix = (const float*)d_in[3];
    const float* b_ix = (const float*)d_in[4];
    const float* W_fx = (const float*)d_in[5];
    const float* b_fx = (const float*)d_in[6];
    const float* W_cx = (const float*)d_in[7];
    const float* b_cx = (const float*)d_in[8];
    const float* W_ox = (const float*)d_in[9];
    const float* b_ox = (const float*)d_in[10];
    const float* W_ih = (const float*)d_in[11];
    const float* b_ih = (const float*)d_in[12];
    const float* W_ic = (const float*)d_in[13];
    const float* b_ic = (const float*)d_in[14];
    const float* W_fh = (const float*)d_in[15];
    const float* b_fh = (const float*)d_in[16];
    const float* W_fc = (const float*)d_in[17];
    const float* b_fc = (const float*)d_in[18];
    const float* W_ch = (const float*)d_in[19];
    const float* b_ch = (const float*)d_in[20];
    const float* W_oh = (const float*)d_in[21];
    const float* b_oh = (const float*)d_in[22];
    const float* W_oc = (const float*)d_in[23];
    const float* b_oc = (const float*)d_in[24];
    float* out = (float*)d_out;

    static int attr_done = 0;
    if (!attr_done) {
        cudaFuncSetAttribute(gemm_kernel, cudaFuncAttributeMaxDynamicSharedMemorySize, SMEM_DYN);
        attr_done = 1;
    }

    pack_A1<<<2048, 256>>>(x, h, c);
    pack_W1<<<8192, 256>>>(W_ix, W_fx, W_cx, W_ox, W_ih, W_ic, W_fh, W_fc, W_ch, W_oh);
    pack_W2<<<1024, 256>>>(W_oc);

    dim3 g1(BB / BM, N1 / BN);   // 32 x 32
    gemm_kernel<<<g1, 256, SMEM_DYN>>>(0);

    ew1<<<4096, 256>>>(c, b_ix, b_ih, b_ic, b_fx, b_fh, b_fc, b_cx, b_ch, out);

    dim3 g2(BB / BM, HH / BN);   // 32 x 8
    gemm_kernel<<<g2, 256, SMEM_DYN>>>(1);

    ew2<<<4096, 256>>>(b_ox, b_oh, b_oc, out);
}